// round 1
// baseline (speedup 1.0000x reference)
#include <cuda_runtime.h>
#include <cstdint>

#define ND 128
#define ED 32
#define HD 256
#define N_MAX 100000
#define E_MAX 1600000

// ---------------- scratch (static device globals; no allocation) ----------------
__device__ int   g_src[E_MAX];
__device__ int   g_dst[E_MAX];
__device__ float g_Psrc[(size_t)N_MAX * HD];  // x@W1[0:128]   + cong*W1[288]
__device__ float g_Pdst[(size_t)N_MAX * HD];  // x@W1[128:256] + mb1
__device__ float g_agg [(size_t)N_MAX * ND];  // scatter-add target

// =================== K0: edge_index convert (int64 OR int32) ===================
// JAX may emit edge_index as int64 or (x64-disabled) int32. Detect at runtime:
// for little-endian int64 values < 2^31, every odd int32 word is 0.
__global__ void k_convert(const int* __restrict__ w, int E)
{
    __shared__ int s64;
    if (threadIdx.x == 0) {
        int b = 1;
        #pragma unroll
        for (int i = 0; i < 8; i++) if (w[2 * i + 1] != 0) b = 0;
        s64 = b;
    }
    __syncthreads();
    int i = blockIdx.x * blockDim.x + threadIdx.x;
    if (i >= E) return;
    if (s64) {
        const long long* e = (const long long*)w;
        g_src[i] = (int)e[i];
        g_dst[i] = (int)e[(size_t)E + i];
    } else {
        g_src[i] = w[i];
        g_dst[i] = w[(size_t)E + i];
    }
}

// =================== K1: per-node precompute of layer-1 partials ===============
// Psrc[n] = x[n] @ mW1[0:128]   + congestion[n] * mW1[288]
// Pdst[n] = x[n] @ mW1[128:256] + mb1
// Also zeroes g_agg.
__global__ __launch_bounds__(256) void k_node_pre(
    const float* __restrict__ x, const float* __restrict__ cong,
    const float* __restrict__ mW1, const float* __restrict__ mb1, int N)
{
    __shared__ float Xt[ND * 33];     // x tile transposed [k][n], pad 33
    __shared__ float Bs[16 * HD];     // weight chunk [16][256]
    const int tid = threadIdx.x;
    const int cg = tid & 31, eg = tid >> 5;
    const int base = blockIdx.x * 32;

    for (int idx = tid; idx < 32 * ND; idx += 256) {
        int k = idx & (ND - 1), n = idx >> 7;
        int node = base + n;
        Xt[k * 33 + n] = (node < N) ? x[(size_t)node * ND + k] : 0.f;
    }
    float cg4[4];
    #pragma unroll
    for (int i = 0; i < 4; i++) {
        int node = base + eg * 4 + i;
        cg4[i] = (node < N) ? cong[node] : 0.f;
    }
    __syncthreads();

    for (int which = 0; which < 2; which++) {
        const float* W = mW1 + (size_t)which * ND * HD;
        float acc[4][8];
        #pragma unroll
        for (int i = 0; i < 4; i++)
            #pragma unroll
            for (int u = 0; u < 8; u++) acc[i][u] = 0.f;

        for (int ko = 0; ko < ND; ko += 16) {
            for (int idx = tid; idx < 16 * HD; idx += 256)
                Bs[idx] = W[(size_t)(ko + (idx >> 8)) * HD + (idx & (HD - 1))];
            __syncthreads();
            #pragma unroll 4
            for (int kk = 0; kk < 16; kk++) {
                float a[4];
                #pragma unroll
                for (int i = 0; i < 4; i++) a[i] = Xt[(ko + kk) * 33 + eg * 4 + i];
                #pragma unroll
                for (int u = 0; u < 8; u++) {
                    float b = Bs[kk * HD + cg + 32 * u];
                    #pragma unroll
                    for (int i = 0; i < 4; i++) acc[i][u] += a[i] * b;
                }
            }
            __syncthreads();
        }
        if (which == 0) {
            #pragma unroll
            for (int u = 0; u < 8; u++) {
                int j = cg + 32 * u;
                float w288 = mW1[(size_t)288 * HD + j];
                #pragma unroll
                for (int i = 0; i < 4; i++) {
                    int node = base + eg * 4 + i;
                    if (node < N) g_Psrc[(size_t)node * HD + j] = acc[i][u] + cg4[i] * w288;
                }
            }
        } else {
            #pragma unroll
            for (int u = 0; u < 8; u++) {
                int j = cg + 32 * u;
                float b1 = mb1[j];
                #pragma unroll
                for (int i = 0; i < 4; i++) {
                    int node = base + eg * 4 + i;
                    if (node < N) g_Pdst[(size_t)node * HD + j] = acc[i][u] + b1;
                }
            }
        }
    }
    // zero aggregation buffer for this tile's nodes
    for (int idx = tid; idx < 32 * ND; idx += 256) {
        int node = base + (idx >> 7);
        if (node < N) g_agg[(size_t)node * ND + (idx & (ND - 1))] = 0.f;
    }
}

// =================== K2: fused edge kernel ======================================
// Per 32-edge tile: h = relu(Psrc[src] + Pdst[dst] + edge_attr@W1c)   [32,256]
//                   msg = h @ mW2 + mb2; atomicAdd into g_agg[dst]
// dyn smem layout (floats):
//   [0,1056)      EAt  [32k][33]       \  aliased by
//   [1056,9248)   Wc   [32][256]       /  Ht [256][33] = [0,8448)
//   [9248,13344)  B2   [32][128]
//   [13344,13408) s_src[32], s_dst[32]
#define K2_SMEM (13408 * 4)
__global__ __launch_bounds__(256) void k_edge(
    const float* __restrict__ edge_attr,
    const float* __restrict__ mW1, const float* __restrict__ mW2,
    const float* __restrict__ mb2, int E)
{
    extern __shared__ float sm[];
    float* EAt = sm;
    float* Wc  = sm + 1056;
    float* Ht  = sm;          // alias (valid after sync)
    float* B2  = sm + 9248;
    int* s_src = (int*)(sm + 13344);
    int* s_dst = s_src + 32;

    const int tid = threadIdx.x;
    const int cg = tid & 31, eg = tid >> 5;
    const int base = blockIdx.x * 32;

    if (tid < 32) {
        int e = base + tid;
        s_src[tid] = (e < E) ? g_src[e] : 0;
        s_dst[tid] = (e < E) ? g_dst[e] : 0;
    }
    for (int idx = tid; idx < 32 * ED; idx += 256) {
        int k = idx & 31, e = idx >> 5;
        EAt[k * 33 + e] = (base + e < E) ? edge_attr[(size_t)(base + e) * ED + k] : 0.f;
    }
    for (int idx = tid; idx < 32 * HD; idx += 256)
        Wc[idx] = mW1[(size_t)(2 * ND + (idx >> 8)) * HD + (idx & (HD - 1))];
    __syncthreads();

    // ---- layer 1 edge part: acc = EA @ W1c ----
    float acc[4][8];
    #pragma unroll
    for (int i = 0; i < 4; i++)
        #pragma unroll
        for (int u = 0; u < 8; u++) acc[i][u] = 0.f;
    #pragma unroll 4
    for (int kk = 0; kk < 32; kk++) {
        float a[4];
        #pragma unroll
        for (int i = 0; i < 4; i++) a[i] = EAt[kk * 33 + eg * 4 + i];
        #pragma unroll
        for (int u = 0; u < 8; u++) {
            float b = Wc[kk * HD + cg + 32 * u];
            #pragma unroll
            for (int i = 0; i < 4; i++) acc[i][u] += a[i] * b;
        }
    }
    __syncthreads();   // EAt/Wc dead; safe to write Ht (aliased)

    // ---- gather node partials, relu, stage h transposed ----
    #pragma unroll
    for (int i = 0; i < 4; i++) {
        int e = eg * 4 + i;
        if (base + e < E) {
            size_t sp = (size_t)s_src[e] * HD;
            size_t dp = (size_t)s_dst[e] * HD;
            #pragma unroll
            for (int u = 0; u < 8; u++) {
                int j = cg + 32 * u;
                float v = acc[i][u] + g_Psrc[sp + j] + g_Pdst[dp + j];
                Ht[j * 33 + e] = fmaxf(v, 0.f);
            }
        } else {
            #pragma unroll
            for (int u = 0; u < 8; u++) Ht[(cg + 32 * u) * 33 + e] = 0.f;
        }
    }
    __syncthreads();

    // ---- layer 2: msg = h @ mW2 ----
    float acc2[4][4];
    #pragma unroll
    for (int i = 0; i < 4; i++)
        #pragma unroll
        for (int u = 0; u < 4; u++) acc2[i][u] = 0.f;
    float bias2[4];
    #pragma unroll
    for (int u = 0; u < 4; u++) bias2[u] = mb2[cg + 32 * u];

    for (int ko = 0; ko < HD; ko += 32) {
        for (int idx = tid; idx < 32 * ND; idx += 256)
            B2[idx] = mW2[(size_t)(ko + (idx >> 7)) * ND + (idx & (ND - 1))];
        __syncthreads();
        #pragma unroll 4
        for (int kk = 0; kk < 32; kk++) {
            float a[4];
            #pragma unroll
            for (int i = 0; i < 4; i++) a[i] = Ht[(ko + kk) * 33 + eg * 4 + i];
            #pragma unroll
            for (int u = 0; u < 4; u++) {
                float b = B2[kk * ND + cg + 32 * u];
                #pragma unroll
                for (int i = 0; i < 4; i++) acc2[i][u] += a[i] * b;
            }
        }
        __syncthreads();
    }

    // ---- scatter-add into destination nodes ----
    #pragma unroll
    for (int i = 0; i < 4; i++) {
        int e = eg * 4 + i;
        if (base + e < E) {
            size_t dp = (size_t)s_dst[e] * ND;
            #pragma unroll
            for (int u = 0; u < 4; u++)
                atomicAdd(&g_agg[dp + cg + 32 * u], acc2[i][u] + bias2[u]);
        }
    }
}

// =================== K3: node update MLP ========================================
// x_new = relu([x, agg] @ uW1 + ub1) @ uW2 + ub2
// dyn smem (floats): At/Ht alias [256][33] = [0,8448); Ws/B2 alias [8448,16640)
#define K3_SMEM (16640 * 4)
__global__ __launch_bounds__(256) void k_update(
    const float* __restrict__ x,
    const float* __restrict__ uW1, const float* __restrict__ ub1,
    const float* __restrict__ uW2, const float* __restrict__ ub2,
    float* __restrict__ out, int N)
{
    extern __shared__ float sm[];
    float* At = sm;
    float* Ht = sm;           // alias (written after layer-1 reads complete)
    float* Ws = sm + 8448;
    float* B2 = sm + 8448;    // alias (Ws dead after layer 1)

    const int tid = threadIdx.x;
    const int cg = tid & 31, eg = tid >> 5;
    const int base = blockIdx.x * 32;

    // stage concat(x, agg) transposed
    for (int idx = tid; idx < 32 * HD; idx += 256) {
        int k = idx & (HD - 1), n = idx >> 8;
        int node = base + n;
        float v = 0.f;
        if (node < N)
            v = (k < ND) ? x[(size_t)node * ND + k]
                         : g_agg[(size_t)node * ND + (k - ND)];
        At[k * 33 + n] = v;
    }
    __syncthreads();

    // ---- layer 1 ----
    float acc[4][8];
    #pragma unroll
    for (int i = 0; i < 4; i++)
        #pragma unroll
        for (int u = 0; u < 8; u++) acc[i][u] = 0.f;

    for (int ko = 0; ko < HD; ko += 32) {
        for (int idx = tid; idx < 32 * HD; idx += 256)
            Ws[idx] = uW1[(size_t)(ko + (idx >> 8)) * HD + (idx & (HD - 1))];
        __syncthreads();
        #pragma unroll 4
        for (int kk = 0; kk < 32; kk++) {
            float a[4];
            #pragma unroll
            for (int i = 0; i < 4; i++) a[i] = At[(ko + kk) * 33 + eg * 4 + i];
            #pragma unroll
            for (int u = 0; u < 8; u++) {
                float b = Ws[kk * HD + cg + 32 * u];
                #pragma unroll
                for (int i = 0; i < 4; i++) acc[i][u] += a[i] * b;
            }
        }
        __syncthreads();
    }

    // relu + bias, stage h transposed (aliases At; all reads done)
    #pragma unroll
    for (int u = 0; u < 8; u++) {
        int j = cg + 32 * u;
        float b1 = ub1[j];
        #pragma unroll
        for (int i = 0; i < 4; i++) {
            int n = eg * 4 + i;
            float v = (base + n < N) ? fmaxf(acc[i][u] + b1, 0.f) : 0.f;
            Ht[j * 33 + n] = v;
        }
    }
    __syncthreads();

    // ---- layer 2 ----
    float acc2[4][4];
    #pragma unroll
    for (int i = 0; i < 4; i++)
        #pragma unroll
        for (int u = 0; u < 4; u++) acc2[i][u] = 0.f;

    for (int ko = 0; ko < HD; ko += 32) {
        for (int idx = tid; idx < 32 * ND; idx += 256)
            B2[idx] = uW2[(size_t)(ko + (idx >> 7)) * ND + (idx & (ND - 1))];
        __syncthreads();
        #pragma unroll 4
        for (int kk = 0; kk < 32; kk++) {
            float a[4];
            #pragma unroll
            for (int i = 0; i < 4; i++) a[i] = Ht[(ko + kk) * 33 + eg * 4 + i];
            #pragma unroll
            for (int u = 0; u < 4; u++) {
                float b = B2[kk * ND + cg + 32 * u];
                #pragma unroll
                for (int i = 0; i < 4; i++) acc2[i][u] += a[i] * b;
            }
        }
        __syncthreads();
    }

    #pragma unroll
    for (int u = 0; u < 4; u++) {
        int j = cg + 32 * u;
        float b2 = ub2[j];
        #pragma unroll
        for (int i = 0; i < 4; i++) {
            int node = base + eg * 4 + i;
            if (node < N) out[(size_t)node * ND + j] = acc2[i][u] + b2;
        }
    }
}

// =================== launcher ===================================================
extern "C" void kernel_launch(void* const* d_in, const int* in_sizes, int n_in,
                              void* d_out, int out_size)
{
    const float* x    = (const float*)d_in[0];
    const int*   ei   = (const int*)  d_in[1];
    const float* ea   = (const float*)d_in[2];
    const float* cong = (const float*)d_in[3];
    const float* mW1  = (const float*)d_in[4];
    const float* mb1  = (const float*)d_in[5];
    const float* mW2  = (const float*)d_in[6];
    const float* mb2  = (const float*)d_in[7];
    const float* uW1  = (const float*)d_in[8];
    const float* ub1  = (const float*)d_in[9];
    const float* uW2  = (const float*)d_in[10];
    const float* ub2  = (const float*)d_in[11];

    int N = in_sizes[0] / ND;
    int E = in_sizes[1] / 2;
    if (N > N_MAX) N = N_MAX;
    if (E > E_MAX) E = E_MAX;

    cudaFuncSetAttribute(k_edge,   cudaFuncAttributeMaxDynamicSharedMemorySize, K2_SMEM);
    cudaFuncSetAttribute(k_update, cudaFuncAttributeMaxDynamicSharedMemorySize, K3_SMEM);

    k_convert <<<(E + 255) / 256, 256>>>(ei, E);
    k_node_pre<<<(N + 31) / 32, 256>>>(x, cong, mW1, mb1, N);
    k_edge    <<<(E + 31) / 32, 256, K2_SMEM>>>(ea, mW1, mW2, mb2, E);
    k_update  <<<(N + 31) / 32, 256, K3_SMEM>>>(x, uW1, ub1, uW2, ub2, (float*)d_out, N);
}

// round 2
// speedup vs baseline: 1.0599x; 1.0599x over previous
#include <cuda_runtime.h>
#include <cstdint>

#define ND 128
#define ED 32
#define HD 256
#define N_MAX 100000
#define E_MAX 1600000

typedef unsigned long long u64;

// ---------------- packed f32x2 helpers ----------------
__device__ __forceinline__ u64 ffma2(u64 a, u64 b, u64 c) {
    u64 d;
    asm("fma.rn.f32x2 %0, %1, %2, %3;" : "=l"(d) : "l"(a), "l"(b), "l"(c));
    return d;
}
__device__ __forceinline__ u64 dup2(float x) {
    u64 d;
    asm("mov.b64 %0, {%1, %1};" : "=l"(d) : "f"(x));
    return d;
}
__device__ __forceinline__ float2 unpk(u64 p) {
    float2 r;
    asm("mov.b64 {%0, %1}, %2;" : "=f"(r.x), "=f"(r.y) : "l"(p));
    return r;
}

// ---------------- scratch (static device globals; no allocation) ----------------
__device__ int   g_src[E_MAX];
__device__ int   g_dst[E_MAX];
__device__ float g_Psrc[(size_t)N_MAX * HD];  // x@W1[0:128]   + cong*W1[288]
__device__ float g_Pdst[(size_t)N_MAX * HD];  // x@W1[128:256] + mb1
__device__ float g_agg [(size_t)N_MAX * ND];  // scatter-add target

// =================== K0: edge_index convert (int64 OR int32) ===================
__global__ void k_convert(const int* __restrict__ w, int E)
{
    __shared__ int s64;
    if (threadIdx.x == 0) {
        int b = 1;
        #pragma unroll
        for (int i = 0; i < 8; i++) if (w[2 * i + 1] != 0) b = 0;
        s64 = b;
    }
    __syncthreads();
    int i = blockIdx.x * blockDim.x + threadIdx.x;
    if (i >= E) return;
    if (s64) {
        const long long* e = (const long long*)w;
        g_src[i] = (int)e[i];
        g_dst[i] = (int)e[(size_t)E + i];
    } else {
        g_src[i] = w[i];
        g_dst[i] = w[(size_t)E + i];
    }
}

// =================== K1: per-node precompute of layer-1 partials ===============
// Psrc[n] = x[n] @ mW1[0:128]   + congestion[n] * mW1[288]
// Pdst[n] = x[n] @ mW1[128:256] + mb1           ; also zeroes g_agg
// Thread output columns: j = 128*p + 4*cg + q   (p in 0..1, q in 0..3)
__global__ __launch_bounds__(256) void k_node_pre(
    const float* __restrict__ x, const float* __restrict__ cong,
    const float* __restrict__ mW1, const float* __restrict__ mb1, int N)
{
    __shared__ __align__(16) float Xt[ND * 33];   // x tile transposed [k][n]
    __shared__ __align__(16) float Bs[16 * HD];   // weight chunk [16][256]
    const int tid = threadIdx.x;
    const int cg = tid & 31, eg = tid >> 5;
    const int base = blockIdx.x * 32;

    for (int idx = tid; idx < 32 * ND; idx += 256) {
        int k = idx & (ND - 1), n = idx >> 7;
        int node = base + n;
        Xt[k * 33 + n] = (node < N) ? x[(size_t)node * ND + k] : 0.f;
    }
    float cg4[4];
    #pragma unroll
    for (int i = 0; i < 4; i++) {
        int node = base + eg * 4 + i;
        cg4[i] = (node < N) ? cong[node] : 0.f;
    }
    __syncthreads();

    for (int which = 0; which < 2; which++) {
        const float* W = mW1 + (size_t)which * ND * HD;
        u64 acc[4][2][2];
        #pragma unroll
        for (int i = 0; i < 4; i++)
            #pragma unroll
            for (int p = 0; p < 2; p++) { acc[i][p][0] = 0ull; acc[i][p][1] = 0ull; }

        for (int ko = 0; ko < ND; ko += 16) {
            // contiguous copy of 16 full rows
            {
                const float4* srcp = (const float4*)(W + (size_t)ko * HD);
                float4* dstp = (float4*)Bs;
                for (int idx = tid; idx < 16 * HD / 4; idx += 256) dstp[idx] = srcp[idx];
            }
            __syncthreads();
            #pragma unroll 4
            for (int kk = 0; kk < 16; kk++) {
                u64 aa[4];
                #pragma unroll
                for (int i = 0; i < 4; i++) aa[i] = dup2(Xt[(ko + kk) * 33 + eg * 4 + i]);
                #pragma unroll
                for (int p = 0; p < 2; p++) {
                    ulonglong2 b = *(const ulonglong2*)&Bs[kk * HD + 4 * cg + 128 * p];
                    #pragma unroll
                    for (int i = 0; i < 4; i++) {
                        acc[i][p][0] = ffma2(aa[i], b.x, acc[i][p][0]);
                        acc[i][p][1] = ffma2(aa[i], b.y, acc[i][p][1]);
                    }
                }
            }
            __syncthreads();
        }

        #pragma unroll
        for (int p = 0; p < 2; p++) {
            if (which == 0) {
                float4 w2 = *(const float4*)&mW1[(size_t)288 * HD + 128 * p + 4 * cg];
                #pragma unroll
                for (int i = 0; i < 4; i++) {
                    int node = base + eg * 4 + i;
                    if (node < N) {
                        float2 v0 = unpk(acc[i][p][0]), v1 = unpk(acc[i][p][1]);
                        float4 r = make_float4(v0.x + cg4[i] * w2.x, v0.y + cg4[i] * w2.y,
                                               v1.x + cg4[i] * w2.z, v1.y + cg4[i] * w2.w);
                        *(float4*)&g_Psrc[(size_t)node * HD + 128 * p + 4 * cg] = r;
                    }
                }
            } else {
                float4 b1 = *(const float4*)&mb1[128 * p + 4 * cg];
                #pragma unroll
                for (int i = 0; i < 4; i++) {
                    int node = base + eg * 4 + i;
                    if (node < N) {
                        float2 v0 = unpk(acc[i][p][0]), v1 = unpk(acc[i][p][1]);
                        float4 r = make_float4(v0.x + b1.x, v0.y + b1.y,
                                               v1.x + b1.z, v1.y + b1.w);
                        *(float4*)&g_Pdst[(size_t)node * HD + 128 * p + 4 * cg] = r;
                    }
                }
            }
        }
    }
    // zero aggregation buffer for this tile's nodes
    for (int idx = tid; idx < 32 * ND; idx += 256) {
        int node = base + (idx >> 7);
        if (node < N) g_agg[(size_t)node * ND + (idx & (ND - 1))] = 0.f;
    }
}

// =================== K2: fused edge kernel ======================================
// h = relu(Psrc[src] + Pdst[dst] + EA@W1c); msg = h@mW2 + mb2 -> red.v4 into g_agg
// dyn smem (floats): EAt[0,1056) Wc[1056,9248) | Ht alias [0,8448) | B2[9248,13344)
//                    s_src/s_dst [13344,13408)
#define K2_SMEM (13408 * 4)
__global__ __launch_bounds__(256) void k_edge(
    const float* __restrict__ edge_attr,
    const float* __restrict__ mW1, const float* __restrict__ mW2,
    const float* __restrict__ mb2, int E)
{
    extern __shared__ __align__(16) float sm[];
    float* EAt = sm;
    float* Wc  = sm + 1056;
    float* Ht  = sm;          // alias (valid after sync)
    float* B2  = sm + 9248;
    int* s_src = (int*)(sm + 13344);
    int* s_dst = s_src + 32;

    const int tid = threadIdx.x;
    const int cg = tid & 31, eg = tid >> 5;
    const int base = blockIdx.x * 32;

    if (tid < 32) {
        int e = base + tid;
        s_src[tid] = (e < E) ? g_src[e] : 0;
        s_dst[tid] = (e < E) ? g_dst[e] : 0;
    }
    for (int idx = tid; idx < 32 * ED; idx += 256) {
        int k = idx & 31, e = idx >> 5;
        EAt[k * 33 + e] = (base + e < E) ? edge_attr[(size_t)(base + e) * ED + k] : 0.f;
    }
    {   // contiguous copy of W1c = mW1[256:288] (32 rows x 256)
        const float4* srcp = (const float4*)(mW1 + (size_t)2 * ND * HD);
        float4* dstp = (float4*)Wc;
        for (int idx = tid; idx < 32 * HD / 4; idx += 256) dstp[idx] = srcp[idx];
    }
    __syncthreads();

    // ---- layer 1 edge part: acc = EA @ W1c ----
    u64 acc[4][2][2];
    #pragma unroll
    for (int i = 0; i < 4; i++)
        #pragma unroll
        for (int p = 0; p < 2; p++) { acc[i][p][0] = 0ull; acc[i][p][1] = 0ull; }
    #pragma unroll 4
    for (int kk = 0; kk < 32; kk++) {
        u64 aa[4];
        #pragma unroll
        for (int i = 0; i < 4; i++) aa[i] = dup2(EAt[kk * 33 + eg * 4 + i]);
        #pragma unroll
        for (int p = 0; p < 2; p++) {
            ulonglong2 b = *(const ulonglong2*)&Wc[kk * HD + 4 * cg + 128 * p];
            #pragma unroll
            for (int i = 0; i < 4; i++) {
                acc[i][p][0] = ffma2(aa[i], b.x, acc[i][p][0]);
                acc[i][p][1] = ffma2(aa[i], b.y, acc[i][p][1]);
            }
        }
    }
    __syncthreads();   // EAt/Wc dead; safe to write Ht (aliased)

    // ---- gather node partials, relu, stage h transposed ----
    #pragma unroll
    for (int i = 0; i < 4; i++) {
        int e = eg * 4 + i;
        if (base + e < E) {
            size_t sp = (size_t)s_src[e] * HD;
            size_t dp = (size_t)s_dst[e] * HD;
            #pragma unroll
            for (int p = 0; p < 2; p++) {
                int jb = 128 * p + 4 * cg;
                float4 ps = *(const float4*)&g_Psrc[sp + jb];
                float4 pd = *(const float4*)&g_Pdst[dp + jb];
                float2 v0 = unpk(acc[i][p][0]), v1 = unpk(acc[i][p][1]);
                Ht[(jb + 0) * 33 + e] = fmaxf(v0.x + ps.x + pd.x, 0.f);
                Ht[(jb + 1) * 33 + e] = fmaxf(v0.y + ps.y + pd.y, 0.f);
                Ht[(jb + 2) * 33 + e] = fmaxf(v1.x + ps.z + pd.z, 0.f);
                Ht[(jb + 3) * 33 + e] = fmaxf(v1.y + ps.w + pd.w, 0.f);
            }
        } else {
            #pragma unroll
            for (int p = 0; p < 2; p++)
                #pragma unroll
                for (int q = 0; q < 4; q++) Ht[(128 * p + 4 * cg + q) * 33 + e] = 0.f;
        }
    }
    __syncthreads();

    // ---- layer 2: msg = h @ mW2  (thread cols j = 4*cg + q) ----
    u64 acc2[4][2];
    #pragma unroll
    for (int i = 0; i < 4; i++) { acc2[i][0] = 0ull; acc2[i][1] = 0ull; }
    float4 b2v = *(const float4*)&mb2[4 * cg];

    for (int ko = 0; ko < HD; ko += 32) {
        {
            const float4* srcp = (const float4*)(mW2 + (size_t)ko * ND);
            float4* dstp = (float4*)B2;
            for (int idx = tid; idx < 32 * ND / 4; idx += 256) dstp[idx] = srcp[idx];
        }
        __syncthreads();
        #pragma unroll 4
        for (int kk = 0; kk < 32; kk++) {
            ulonglong2 b = *(const ulonglong2*)&B2[kk * ND + 4 * cg];
            #pragma unroll
            for (int i = 0; i < 4; i++) {
                u64 aa = dup2(Ht[(ko + kk) * 33 + eg * 4 + i]);
                acc2[i][0] = ffma2(aa, b.x, acc2[i][0]);
                acc2[i][1] = ffma2(aa, b.y, acc2[i][1]);
            }
        }
        __syncthreads();
    }

    // ---- vectorized scatter-add into destination nodes ----
    #pragma unroll
    for (int i = 0; i < 4; i++) {
        int e = eg * 4 + i;
        if (base + e < E) {
            float2 m0 = unpk(acc2[i][0]), m1 = unpk(acc2[i][1]);
            float x0 = m0.x + b2v.x, x1 = m0.y + b2v.y;
            float x2 = m1.x + b2v.z, x3 = m1.y + b2v.w;
            float* ptr = &g_agg[(size_t)s_dst[e] * ND + 4 * cg];
            asm volatile("red.global.add.v4.f32 [%0], {%1, %2, %3, %4};"
                         :: "l"(ptr), "f"(x0), "f"(x1), "f"(x2), "f"(x3) : "memory");
        }
    }
}

// =================== K3: node update MLP ========================================
// x_new = relu([x, agg] @ uW1 + ub1) @ uW2 + ub2
#define K3_SMEM (16640 * 4)
__global__ __launch_bounds__(256) void k_update(
    const float* __restrict__ x,
    const float* __restrict__ uW1, const float* __restrict__ ub1,
    const float* __restrict__ uW2, const float* __restrict__ ub2,
    float* __restrict__ out, int N)
{
    extern __shared__ __align__(16) float sm[];
    float* At = sm;
    float* Ht = sm;           // alias
    float* Ws = sm + 8448;
    float* B2 = sm + 8448;    // alias

    const int tid = threadIdx.x;
    const int cg = tid & 31, eg = tid >> 5;
    const int base = blockIdx.x * 32;

    for (int idx = tid; idx < 32 * HD; idx += 256) {
        int k = idx & (HD - 1), n = idx >> 8;
        int node = base + n;
        float v = 0.f;
        if (node < N)
            v = (k < ND) ? x[(size_t)node * ND + k]
                         : g_agg[(size_t)node * ND + (k - ND)];
        At[k * 33 + n] = v;
    }
    __syncthreads();

    // ---- layer 1 ----
    u64 acc[4][2][2];
    #pragma unroll
    for (int i = 0; i < 4; i++)
        #pragma unroll
        for (int p = 0; p < 2; p++) { acc[i][p][0] = 0ull; acc[i][p][1] = 0ull; }

    for (int ko = 0; ko < HD; ko += 32) {
        {
            const float4* srcp = (const float4*)(uW1 + (size_t)ko * HD);
            float4* dstp = (float4*)Ws;
            for (int idx = tid; idx < 32 * HD / 4; idx += 256) dstp[idx] = srcp[idx];
        }
        __syncthreads();
        #pragma unroll 4
        for (int kk = 0; kk < 32; kk++) {
            u64 aa[4];
            #pragma unroll
            for (int i = 0; i < 4; i++) aa[i] = dup2(At[(ko + kk) * 33 + eg * 4 + i]);
            #pragma unroll
            for (int p = 0; p < 2; p++) {
                ulonglong2 b = *(const ulonglong2*)&Ws[kk * HD + 4 * cg + 128 * p];
                #pragma unroll
                for (int i = 0; i < 4; i++) {
                    acc[i][p][0] = ffma2(aa[i], b.x, acc[i][p][0]);
                    acc[i][p][1] = ffma2(aa[i], b.y, acc[i][p][1]);
                }
            }
        }
        __syncthreads();
    }

    // relu + bias, stage h transposed (aliases At)
    #pragma unroll
    for (int p = 0; p < 2; p++) {
        float4 b1 = *(const float4*)&ub1[128 * p + 4 * cg];
        #pragma unroll
        for (int i = 0; i < 4; i++) {
            int n = eg * 4 + i;
            int jb = 128 * p + 4 * cg;
            float2 v0 = unpk(acc[i][p][0]), v1 = unpk(acc[i][p][1]);
            bool ok = (base + n < N);
            Ht[(jb + 0) * 33 + n] = ok ? fmaxf(v0.x + b1.x, 0.f) : 0.f;
            Ht[(jb + 1) * 33 + n] = ok ? fmaxf(v0.y + b1.y, 0.f) : 0.f;
            Ht[(jb + 2) * 33 + n] = ok ? fmaxf(v1.x + b1.z, 0.f) : 0.f;
            Ht[(jb + 3) * 33 + n] = ok ? fmaxf(v1.y + b1.w, 0.f) : 0.f;
        }
    }
    __syncthreads();

    // ---- layer 2 (thread cols j = 4*cg + q) ----
    u64 acc2[4][2];
    #pragma unroll
    for (int i = 0; i < 4; i++) { acc2[i][0] = 0ull; acc2[i][1] = 0ull; }

    for (int ko = 0; ko < HD; ko += 32) {
        {
            const float4* srcp = (const float4*)(uW2 + (size_t)ko * ND);
            float4* dstp = (float4*)B2;
            for (int idx = tid; idx < 32 * ND / 4; idx += 256) dstp[idx] = srcp[idx];
        }
        __syncthreads();
        #pragma unroll 4
        for (int kk = 0; kk < 32; kk++) {
            ulonglong2 b = *(const ulonglong2*)&B2[kk * ND + 4 * cg];
            #pragma unroll
            for (int i = 0; i < 4; i++) {
                u64 aa = dup2(Ht[(ko + kk) * 33 + eg * 4 + i]);
                acc2[i][0] = ffma2(aa, b.x, acc2[i][0]);
                acc2[i][1] = ffma2(aa, b.y, acc2[i][1]);
            }
        }
        __syncthreads();
    }

    float4 b2v = *(const float4*)&ub2[4 * cg];
    #pragma unroll
    for (int i = 0; i < 4; i++) {
        int node = base + eg * 4 + i;
        if (node < N) {
            float2 m0 = unpk(acc2[i][0]), m1 = unpk(acc2[i][1]);
            float4 r = make_float4(m0.x + b2v.x, m0.y + b2v.y, m1.x + b2v.z, m1.y + b2v.w);
            *(float4*)&out[(size_t)node * ND + 4 * cg] = r;
        }
    }
}

// =================== launcher ===================================================
extern "C" void kernel_launch(void* const* d_in, const int* in_sizes, int n_in,
                              void* d_out, int out_size)
{
    const float* x    = (const float*)d_in[0];
    const int*   ei   = (const int*)  d_in[1];
    const float* ea   = (const float*)d_in[2];
    const float* cong = (const float*)d_in[3];
    const float* mW1  = (const float*)d_in[4];
    const float* mb1  = (const float*)d_in[5];
    const float* mW2  = (const float*)d_in[6];
    const float* mb2  = (const float*)d_in[7];
    const float* uW1  = (const float*)d_in[8];
    const float* ub1  = (const float*)d_in[9];
    const float* uW2  = (const float*)d_in[10];
    const float* ub2  = (const float*)d_in[11];

    int N = in_sizes[0] / ND;
    int E = in_sizes[1] / 2;
    if (N > N_MAX) N = N_MAX;
    if (E > E_MAX) E = E_MAX;

    cudaFuncSetAttribute(k_edge,   cudaFuncAttributeMaxDynamicSharedMemorySize, K2_SMEM);
    cudaFuncSetAttribute(k_update, cudaFuncAttributeMaxDynamicSharedMemorySize, K3_SMEM);

    k_convert <<<(E + 255) / 256, 256>>>(ei, E);
    k_node_pre<<<(N + 31) / 32, 256>>>(x, cong, mW1, mb1, N);
    k_edge    <<<(E + 31) / 32, 256, K2_SMEM>>>(ea, mW1, mW2, mb2, E);
    k_update  <<<(N + 31) / 32, 256, K3_SMEM>>>(x, uW1, ub1, uW2, ub2, (float*)d_out, N);
}

// round 4
// speedup vs baseline: 1.3020x; 1.2284x over previous
#include <cuda_runtime.h>
#include <cuda_bf16.h>
#include <cstdint>

#define ND 128
#define ED 32
#define HD 256
#define N_MAX 100000
#define E_MAX 1600000

typedef unsigned long long u64;
typedef unsigned int u32;

// ---------------- packed f32x2 helpers (scalar kernels) ----------------
__device__ __forceinline__ u64 ffma2(u64 a, u64 b, u64 c) {
    u64 d;
    asm("fma.rn.f32x2 %0, %1, %2, %3;" : "=l"(d) : "l"(a), "l"(b), "l"(c));
    return d;
}
__device__ __forceinline__ u64 dup2(float x) {
    u64 d;
    asm("mov.b64 %0, {%1, %1};" : "=l"(d) : "f"(x));
    return d;
}
__device__ __forceinline__ float2 unpk(u64 p) {
    float2 r;
    asm("mov.b64 {%0, %1}, %2;" : "=f"(r.x), "=f"(r.y) : "l"(p));
    return r;
}

// ---------------- warp-MMA helpers (family-compatible: sm_80+) ----------------
__device__ __forceinline__ u32 smem_u32(const void* p) {
    u32 a;
    asm("{ .reg .u64 t; cvta.to.shared.u64 t, %1; cvt.u32.u64 %0, t; }" : "=r"(a) : "l"(p));
    return a;
}
__device__ __forceinline__ void ldsm_x4(u32 addr, u32& r0, u32& r1, u32& r2, u32& r3) {
    asm volatile("ldmatrix.sync.aligned.m8n8.x4.shared.b16 {%0,%1,%2,%3}, [%4];"
        : "=r"(r0), "=r"(r1), "=r"(r2), "=r"(r3) : "r"(addr));
}
__device__ __forceinline__ void mma_bf16(float* d, u32 a0, u32 a1, u32 a2, u32 a3,
                                         u32 b0, u32 b1) {
    asm volatile("mma.sync.aligned.m16n8k16.row.col.f32.bf16.bf16.f32 "
        "{%0,%1,%2,%3}, {%4,%5,%6,%7}, {%8,%9}, {%0,%1,%2,%3};"
        : "+f"(d[0]), "+f"(d[1]), "+f"(d[2]), "+f"(d[3])
        : "r"(a0), "r"(a1), "r"(a2), "r"(a3), "r"(b0), "r"(b1));
}
__device__ __forceinline__ void bfsplit2(float a, float b, u32& hi, u32& lo) {
    __nv_bfloat162 h = __floats2bfloat162_rn(a, b);
    float ra = a - __bfloat162float(h.x);
    float rb = b - __bfloat162float(h.y);
    __nv_bfloat162 l = __floats2bfloat162_rn(ra, rb);
    hi = *(u32*)&h;
    lo = *(u32*)&l;
}

// ---------------- scratch ----------------
__device__ int   g_src[E_MAX];
__device__ int   g_dst[E_MAX];
__device__ float g_Psrc[(size_t)N_MAX * HD];
__device__ float g_Pdst[(size_t)N_MAX * HD];
__device__ float g_agg [(size_t)N_MAX * ND];
// pre-split bf16 weight images (plain row-major, [n][k])
__device__ __align__(16) __nv_bfloat16 g_B1e[256 * 64];   // k<32: W1c_hi, k>=32: W1c_lo
__device__ __align__(16) __nv_bfloat16 g_B2e[128 * 512];  // k<256: W2_hi,  k>=256: W2_lo

// =================== K0: edge_index convert (int64 OR int32) ===================
__global__ void k_convert(const int* __restrict__ w, int E)
{
    __shared__ int s64;
    if (threadIdx.x == 0) {
        int b = 1;
        #pragma unroll
        for (int i = 0; i < 8; i++) if (w[2 * i + 1] != 0) b = 0;
        s64 = b;
    }
    __syncthreads();
    int i = blockIdx.x * blockDim.x + threadIdx.x;
    if (i >= E) return;
    if (s64) {
        const long long* e = (const long long*)w;
        g_src[i] = (int)e[i];
        g_dst[i] = (int)e[(size_t)E + i];
    } else {
        g_src[i] = w[i];
        g_dst[i] = w[(size_t)E + i];
    }
}

// =================== K_prep: build pre-split bf16 weight images =================
__global__ void k_prep(const float* __restrict__ mW1, const float* __restrict__ mW2)
{
    int tid = blockIdx.x * blockDim.x + threadIdx.x;
    int total = 256 * 32 + 128 * 256;
    for (int i = tid; i < total; i += gridDim.x * blockDim.x) {
        if (i < 256 * 32) {
            int n = i >> 5, k = i & 31;                 // W1c[k][n]
            float w = mW1[(size_t)(2 * ND + k) * HD + n];
            __nv_bfloat16 h = __float2bfloat16(w);
            __nv_bfloat16 l = __float2bfloat16(w - __bfloat162float(h));
            g_B1e[n * 64 + k]      = h;
            g_B1e[n * 64 + 32 + k] = l;
        } else {
            int q = i - 256 * 32;
            int n = q >> 8, j = q & 255;                // W2[j][n]
            float w = mW2[(size_t)j * ND + n];
            __nv_bfloat16 h = __float2bfloat16(w);
            __nv_bfloat16 l = __float2bfloat16(w - __bfloat162float(h));
            g_B2e[n * 512 + j]       = h;
            g_B2e[n * 512 + 256 + j] = l;
        }
    }
}

// =================== K1: per-node precompute (scalar, proven) ===================
__global__ __launch_bounds__(256) void k_node_pre(
    const float* __restrict__ x, const float* __restrict__ cong,
    const float* __restrict__ mW1, const float* __restrict__ mb1, int N)
{
    __shared__ __align__(16) float Xt[ND * 33];
    __shared__ __align__(16) float Bs[16 * HD];
    const int tid = threadIdx.x;
    const int cg = tid & 31, eg = tid >> 5;
    const int base = blockIdx.x * 32;

    for (int idx = tid; idx < 32 * ND; idx += 256) {
        int k = idx & (ND - 1), n = idx >> 7;
        int node = base + n;
        Xt[k * 33 + n] = (node < N) ? x[(size_t)node * ND + k] : 0.f;
    }
    float cg4[4];
    #pragma unroll
    for (int i = 0; i < 4; i++) {
        int node = base + eg * 4 + i;
        cg4[i] = (node < N) ? cong[node] : 0.f;
    }
    __syncthreads();

    for (int which = 0; which < 2; which++) {
        const float* W = mW1 + (size_t)which * ND * HD;
        u64 acc[4][2][2];
        #pragma unroll
        for (int i = 0; i < 4; i++)
            #pragma unroll
            for (int p = 0; p < 2; p++) { acc[i][p][0] = 0ull; acc[i][p][1] = 0ull; }

        for (int ko = 0; ko < ND; ko += 16) {
            {
                const float4* srcp = (const float4*)(W + (size_t)ko * HD);
                float4* dstp = (float4*)Bs;
                for (int idx = tid; idx < 16 * HD / 4; idx += 256) dstp[idx] = srcp[idx];
            }
            __syncthreads();
            #pragma unroll 4
            for (int kk = 0; kk < 16; kk++) {
                u64 aa[4];
                #pragma unroll
                for (int i = 0; i < 4; i++) aa[i] = dup2(Xt[(ko + kk) * 33 + eg * 4 + i]);
                #pragma unroll
                for (int p = 0; p < 2; p++) {
                    ulonglong2 b = *(const ulonglong2*)&Bs[kk * HD + 4 * cg + 128 * p];
                    #pragma unroll
                    for (int i = 0; i < 4; i++) {
                        acc[i][p][0] = ffma2(aa[i], b.x, acc[i][p][0]);
                        acc[i][p][1] = ffma2(aa[i], b.y, acc[i][p][1]);
                    }
                }
            }
            __syncthreads();
        }
        #pragma unroll
        for (int p = 0; p < 2; p++) {
            if (which == 0) {
                float4 w2 = *(const float4*)&mW1[(size_t)288 * HD + 128 * p + 4 * cg];
                #pragma unroll
                for (int i = 0; i < 4; i++) {
                    int node = base + eg * 4 + i;
                    if (node < N) {
                        float2 v0 = unpk(acc[i][p][0]), v1 = unpk(acc[i][p][1]);
                        float4 r = make_float4(v0.x + cg4[i] * w2.x, v0.y + cg4[i] * w2.y,
                                               v1.x + cg4[i] * w2.z, v1.y + cg4[i] * w2.w);
                        *(float4*)&g_Psrc[(size_t)node * HD + 128 * p + 4 * cg] = r;
                    }
                }
            } else {
                float4 b1 = *(const float4*)&mb1[128 * p + 4 * cg];
                #pragma unroll
                for (int i = 0; i < 4; i++) {
                    int node = base + eg * 4 + i;
                    if (node < N) {
                        float2 v0 = unpk(acc[i][p][0]), v1 = unpk(acc[i][p][1]);
                        float4 r = make_float4(v0.x + b1.x, v0.y + b1.y,
                                               v1.x + b1.z, v1.y + b1.w);
                        *(float4*)&g_Pdst[(size_t)node * HD + 128 * p + 4 * cg] = r;
                    }
                }
            }
        }
    }
    for (int idx = tid; idx < 32 * ND; idx += 256) {
        int node = base + (idx >> 7);
        if (node < N) g_agg[(size_t)node * ND + (idx & (ND - 1))] = 0.f;
    }
}

// =================== K2: warp-MMA edge kernel ===================================
// 128 edges/CTA, 8 warps. bf16 hi/lo 3-term split on HMMA (mma.sync m16n8k16).
// smem (bytes):
//   A1  @ 0       [128 rows][72 halves]   stride 144   18432
//   B1  @ 18432   [256 rows][72 halves]   stride 144   36864
//   A2  @ 55296   [128 rows][520 halves]  stride 1040  133120  (k: 0-255 h_hi, 256-511 h_lo)
//   B2s @ 188416  [128 rows][72 halves]   stride 144   18432   (streamed 64-k phases)
//   src @ 206848  int[128];  dst @ 207360 int[128]
#define A1_OFF  0
#define B1_OFF  18432
#define A2_OFF  55296
#define B2S_OFF 188416
#define SRC_OFF 206848
#define DST_OFF 207360
#define TC_SMEM 207872
#define A1_ST 144
#define B1_ST 144
#define A2_ST 1040
#define B2_ST 144

__global__ __launch_bounds__(256, 1) void k_edge_mma(
    const float* __restrict__ edge_attr, const float* __restrict__ mb2, int E)
{
    extern __shared__ __align__(16) char sm[];
    const u32 smu = smem_u32(sm);
    const int tid = threadIdx.x;
    const int w = tid >> 5, l = tid & 31;
    const int g = l >> 2, t = l & 3;
    const int base = blockIdx.x * 128;

    // ---- stage src/dst ----
    if (tid < 128) {
        int e = base + tid;
        ((int*)(sm + SRC_OFF))[tid] = (e < E) ? g_src[e] : 0;
        ((int*)(sm + DST_OFF))[tid] = (e < E) ? g_dst[e] : 0;
    }
    // ---- stage B1 (pre-split image, 128B rows -> 144B stride) ----
    for (int idx = tid; idx < 256 * 8; idx += 256) {
        int row = idx >> 3, ch = idx & 7;
        *(float4*)(sm + B1_OFF + row * B1_ST + ch * 16) =
            *(const float4*)((const char*)g_B1e + row * 128 + ch * 16);
    }
    // ---- stage A1: split edge_attr to bf16 hi|lo ----
    {
        int e = tid >> 1, h = tid & 1;
        char* arow = sm + A1_OFF + e * A1_ST;
        if (base + e < E) {
            const float4* src4 = (const float4*)(edge_attr + (size_t)(base + e) * ED + 16 * h);
            #pragma unroll
            for (int q = 0; q < 4; q++) {
                float4 v = src4[q];
                u32 h0, l0, h1, l1;
                bfsplit2(v.x, v.y, h0, l0);
                bfsplit2(v.z, v.w, h1, l1);
                int k = 16 * h + 4 * q;
                *(u32*)(arow + k * 2)            = h0;
                *(u32*)(arow + (k + 2) * 2)      = h1;
                *(u32*)(arow + (32 + k) * 2)     = l0;
                *(u32*)(arow + (32 + k + 2) * 2) = l1;
            }
        } else {
            #pragma unroll
            for (int q = 0; q < 8; q++) {
                int k = 16 * h + 2 * q;
                *(u32*)(arow + k * 2)        = 0u;
                *(u32*)(arow + (32 + k) * 2) = 0u;
            }
        }
    }
    __syncthreads();

    // per-lane ldmatrix address components
    const int lr   = l & 7;
    const int aRow = 16 * w + lr + ((l >> 3) & 1) * 8;  // A matrices: m, m+8, m, m+8
    const int aKh  = (l >> 4) * 8;                      // A matrices: k, k, k+8, k+8
    const u32 a1base = smu + A1_OFF + aRow * A1_ST + aKh * 2;
    const u32 a2base = smu + A2_OFF + aRow * A2_ST + aKh * 2;
    const int bRow = lr + (l >> 4) * 8;                 // B matrices: n, n, n+8, n+8
    const int bKh  = ((l >> 3) & 1) * 8;                // B matrices: k, k+8, k, k+8

    // A1 fragments (k-tiles 0,16,32,48) cached for all chunks
    u32 fa[4][4];
    #pragma unroll
    for (int kt = 0; kt < 4; kt++)
        ldsm_x4(a1base + kt * 32, fa[kt][0], fa[kt][1], fa[kt][2], fa[kt][3]);

    // this lane's two edge rows
    const int m0 = 16 * w + g, m1 = m0 + 8;
    const int vs0 = ((const int*)(sm + SRC_OFF))[m0];
    const int vd0 = ((const int*)(sm + DST_OFF))[m0];
    const int vs1 = ((const int*)(sm + SRC_OFF))[m1];
    const int vd1 = ((const int*)(sm + DST_OFF))[m1];
    char* a2r0 = sm + A2_OFF + m0 * A2_ST;
    char* a2r1 = sm + A2_OFF + m1 * A2_ST;

    // ---- layer 1 (per 64-col chunk) + fused gather/relu/split epilogue ----
    #pragma unroll 1
    for (int c = 0; c < 4; c++) {
        float acc1[8][4];
        #pragma unroll
        for (int j = 0; j < 8; j++)
            #pragma unroll
            for (int q = 0; q < 4; q++) acc1[j][q] = 0.f;

        #pragma unroll
        for (int jp = 0; jp < 4; jp++) {
            u32 bb = smu + B1_OFF + (64 * c + 16 * jp + bRow) * B1_ST + bKh * 2;
            u32 b0, b1, b2, b3;
            ldsm_x4(bb + 0, b0, b1, b2, b3);      // W1hi k0-15
            mma_bf16(acc1[2 * jp],     fa[0][0], fa[0][1], fa[0][2], fa[0][3], b0, b1);
            mma_bf16(acc1[2 * jp + 1], fa[0][0], fa[0][1], fa[0][2], fa[0][3], b2, b3);
            mma_bf16(acc1[2 * jp],     fa[2][0], fa[2][1], fa[2][2], fa[2][3], b0, b1);
            mma_bf16(acc1[2 * jp + 1], fa[2][0], fa[2][1], fa[2][2], fa[2][3], b2, b3);
            ldsm_x4(bb + 32, b0, b1, b2, b3);     // W1hi k16-31
            mma_bf16(acc1[2 * jp],     fa[1][0], fa[1][1], fa[1][2], fa[1][3], b0, b1);
            mma_bf16(acc1[2 * jp + 1], fa[1][0], fa[1][1], fa[1][2], fa[1][3], b2, b3);
            mma_bf16(acc1[2 * jp],     fa[3][0], fa[3][1], fa[3][2], fa[3][3], b0, b1);
            mma_bf16(acc1[2 * jp + 1], fa[3][0], fa[3][1], fa[3][2], fa[3][3], b2, b3);
            ldsm_x4(bb + 64, b0, b1, b2, b3);     // W1lo k0-15
            mma_bf16(acc1[2 * jp],     fa[0][0], fa[0][1], fa[0][2], fa[0][3], b0, b1);
            mma_bf16(acc1[2 * jp + 1], fa[0][0], fa[0][1], fa[0][2], fa[0][3], b2, b3);
            ldsm_x4(bb + 96, b0, b1, b2, b3);     // W1lo k16-31
            mma_bf16(acc1[2 * jp],     fa[1][0], fa[1][1], fa[1][2], fa[1][3], b0, b1);
            mma_bf16(acc1[2 * jp + 1], fa[1][0], fa[1][1], fa[1][2], fa[1][3], b2, b3);
        }

        // fused epilogue: gather node partials, relu, bf16-split into A2
        #pragma unroll
        for (int nt = 0; nt < 8; nt++) {
            int n = 64 * c + 8 * nt + 2 * t;
            float2 ps0 = *(const float2*)(g_Psrc + (size_t)vs0 * HD + n);
            float2 pd0 = *(const float2*)(g_Pdst + (size_t)vd0 * HD + n);
            float2 ps1 = *(const float2*)(g_Psrc + (size_t)vs1 * HD + n);
            float2 pd1 = *(const float2*)(g_Pdst + (size_t)vd1 * HD + n);
            float v00 = fmaxf(acc1[nt][0] + ps0.x + pd0.x, 0.f);
            float v01 = fmaxf(acc1[nt][1] + ps0.y + pd0.y, 0.f);
            float v10 = fmaxf(acc1[nt][2] + ps1.x + pd1.x, 0.f);
            float v11 = fmaxf(acc1[nt][3] + ps1.y + pd1.y, 0.f);
            u32 h0, l0v, h1, l1v;
            bfsplit2(v00, v01, h0, l0v);
            bfsplit2(v10, v11, h1, l1v);
            *(u32*)(a2r0 + n * 2)         = h0;
            *(u32*)(a2r0 + (256 + n) * 2) = l0v;
            *(u32*)(a2r1 + n * 2)         = h1;
            *(u32*)(a2r1 + (256 + n) * 2) = l1v;
        }
    }

    // ---- layer 2: D2[128,128], K = 768 effective (3-term) ----
    float acc2[16][4];
    #pragma unroll
    for (int j = 0; j < 16; j++)
        #pragma unroll
        for (int q = 0; q < 4; q++) acc2[j][q] = 0.f;

    // pass A: W2hi phases; terms h_hi@W2hi + h_lo@W2hi
    #pragma unroll 1
    for (int c = 0; c < 4; c++) {
        __syncthreads();
        for (int idx = tid; idx < 128 * 8; idx += 256) {
            int row = idx >> 3, ch = idx & 7;
            *(float4*)(sm + B2S_OFF + row * B2_ST + ch * 16) =
                *(const float4*)((const char*)g_B2e + row * 1024 + (64 * c) * 2 + ch * 16);
        }
        __syncthreads();
        #pragma unroll
        for (int t4 = 0; t4 < 4; t4++) {
            u32 ah0, ah1, ah2, ah3, al0, al1, al2, al3;
            ldsm_x4(a2base + (64 * c + 16 * t4) * 2, ah0, ah1, ah2, ah3);
            ldsm_x4(a2base + (256 + 64 * c + 16 * t4) * 2, al0, al1, al2, al3);
            #pragma unroll
            for (int jp = 0; jp < 8; jp++) {
                u32 b0, b1, b2, b3;
                ldsm_x4(smu + B2S_OFF + (16 * jp + bRow) * B2_ST + (16 * t4 + bKh) * 2,
                        b0, b1, b2, b3);
                mma_bf16(acc2[2 * jp],     ah0, ah1, ah2, ah3, b0, b1);
                mma_bf16(acc2[2 * jp + 1], ah0, ah1, ah2, ah3, b2, b3);
                mma_bf16(acc2[2 * jp],     al0, al1, al2, al3, b0, b1);
                mma_bf16(acc2[2 * jp + 1], al0, al1, al2, al3, b2, b3);
            }
        }
    }
    // pass B: W2lo phases; term h_hi@W2lo
    #pragma unroll 1
    for (int c = 0; c < 4; c++) {
        __syncthreads();
        for (int idx = tid; idx < 128 * 8; idx += 256) {
            int row = idx >> 3, ch = idx & 7;
            *(float4*)(sm + B2S_OFF + row * B2_ST + ch * 16) =
                *(const float4*)((const char*)g_B2e + row * 1024 + (256 + 64 * c) * 2 + ch * 16);
        }
        __syncthreads();
        #pragma unroll
        for (int t4 = 0; t4 < 4; t4++) {
            u32 ah0, ah1, ah2, ah3;
            ldsm_x4(a2base + (64 * c + 16 * t4) * 2, ah0, ah1, ah2, ah3);
            #pragma unroll
            for (int jp = 0; jp < 8; jp++) {
                u32 b0, b1, b2, b3;
                ldsm_x4(smu + B2S_OFF + (16 * jp + bRow) * B2_ST + (16 * t4 + bKh) * 2,
                        b0, b1, b2, b3);
                mma_bf16(acc2[2 * jp],     ah0, ah1, ah2, ah3, b0, b1);
                mma_bf16(acc2[2 * jp + 1], ah0, ah1, ah2, ah3, b2, b3);
            }
        }
    }

    // ---- scatter: + mb2, red.v2 into g_agg[dst] ----
    const bool e0 = (base + m0 < E), e1 = (base + m1 < E);
    #pragma unroll
    for (int nt = 0; nt < 16; nt++) {
        int n = 8 * nt + 2 * t;
        float2 bv = *(const float2*)(mb2 + n);
        if (e0) {
            float x0 = acc2[nt][0] + bv.x, x1 = acc2[nt][1] + bv.y;
            asm volatile("red.global.add.v2.f32 [%0], {%1, %2};"
                         :: "l"(g_agg + (size_t)vd0 * ND + n), "f"(x0), "f"(x1) : "memory");
        }
        if (e1) {
            float x0 = acc2[nt][2] + bv.x, x1 = acc2[nt][3] + bv.y;
            asm volatile("red.global.add.v2.f32 [%0], {%1, %2};"
                         :: "l"(g_agg + (size_t)vd1 * ND + n), "f"(x0), "f"(x1) : "memory");
        }
    }
}

// =================== K3: node update MLP (scalar, proven) =======================
#define K3_SMEM (16640 * 4)
__global__ __launch_bounds__(256) void k_update(
    const float* __restrict__ x,
    const float* __restrict__ uW1, const float* __restrict__ ub1,
    const float* __restrict__ uW2, const float* __restrict__ ub2,
    float* __restrict__ out, int N)
{
    extern __shared__ __align__(16) float smf[];
    float* At = smf;
    float* Ht = smf;
    float* Ws = smf + 8448;
    float* B2 = smf + 8448;

    const int tid = threadIdx.x;
    const int cg = tid & 31, eg = tid >> 5;
    const int base = blockIdx.x * 32;

    for (int idx = tid; idx < 32 * HD; idx += 256) {
        int k = idx & (HD - 1), n = idx >> 8;
        int node = base + n;
        float v = 0.f;
        if (node < N)
            v = (k < ND) ? x[(size_t)node * ND + k]
                         : g_agg[(size_t)node * ND + (k - ND)];
        At[k * 33 + n] = v;
    }
    __syncthreads();

    u64 acc[4][2][2];
    #pragma unroll
    for (int i = 0; i < 4; i++)
        #pragma unroll
        for (int p = 0; p < 2; p++) { acc[i][p][0] = 0ull; acc[i][p][1] = 0ull; }

    for (int ko = 0; ko < HD; ko += 32) {
        {
            const float4* srcp = (const float4*)(uW1 + (size_t)ko * HD);
            float4* dstp = (float4*)Ws;
            for (int idx = tid; idx < 32 * HD / 4; idx += 256) dstp[idx] = srcp[idx];
        }
        __syncthreads();
        #pragma unroll 4
        for (int kk = 0; kk < 32; kk++) {
            u64 aa[4];
            #pragma unroll
            for (int i = 0; i < 4; i++) aa[i] = dup2(At[(ko + kk) * 33 + eg * 4 + i]);
            #pragma unroll
            for (int p = 0; p < 2; p++) {
                ulonglong2 b = *(const ulonglong2*)&Ws[kk * HD + 4 * cg + 128 * p];
                #pragma unroll
                for (int i = 0; i < 4; i++) {
                    acc[i][p][0] = ffma2(aa[i], b.x, acc[i][p][0]);
                    acc[i][p][1] = ffma2(aa[i], b.y, acc[i][p][1]);
                }
            }
        }
        __syncthreads();
    }

    #pragma unroll
    for (int p = 0; p < 2; p++) {
        float4 b1 = *(const float4*)&ub1[128 * p + 4 * cg];
        #pragma unroll
        for (int i = 0; i < 4; i++) {
            int n = eg * 4 + i;
            int jb = 128 * p + 4 * cg;
            float2 v0 = unpk(acc[i][p][0]), v1 = unpk(acc[i][p][1]);
            bool ok = (base + n < N);
            Ht[(jb + 0) * 33 + n] = ok ? fmaxf(v0.x + b1.x, 0.f) : 0.f;
            Ht[(jb + 1) * 33 + n] = ok ? fmaxf(v0.y + b1.y, 0.f) : 0.f;
            Ht[(jb + 2) * 33 + n] = ok ? fmaxf(v1.x + b1.z, 0.f) : 0.f;
            Ht[(jb + 3) * 33 + n] = ok ? fmaxf(v1.y + b1.w, 0.f) : 0.f;
        }
    }
    __syncthreads();

    u64 acc2[4][2];
    #pragma unroll
    for (int i = 0; i < 4; i++) { acc2[i][0] = 0ull; acc2[i][1] = 0ull; }

    for (int ko = 0; ko < HD; ko += 32) {
        {
            const float4* srcp = (const float4*)(uW2 + (size_t)ko * ND);
            float4* dstp = (float4*)B2;
            for (int idx = tid; idx < 32 * ND / 4; idx += 256) dstp[idx] = srcp[idx];
        }
        __syncthreads();
        #pragma unroll 4
        for (int kk = 0; kk < 32; kk++) {
            ulonglong2 b = *(const ulonglong2*)&B2[kk * ND + 4 * cg];
            #pragma unroll
            for (int i = 0; i < 4; i++) {
                u64 aa = dup2(Ht[(ko + kk) * 33 + eg * 4 + i]);
                acc2[i][0] = ffma2(aa, b.x, acc2[i][0]);
                acc2[i][1] = ffma2(aa, b.y, acc2[i][1]);
            }
        }
        __syncthreads();
    }

    float4 b2v = *(const float4*)&ub2[4 * cg];
    #pragma unroll
    for (int i = 0; i < 4; i++) {
        int node = base + eg * 4 + i;
        if (node < N) {
            float2 m0 = unpk(acc2[i][0]), m1 = unpk(acc2[i][1]);
            float4 r = make_float4(m0.x + b2v.x, m0.y + b2v.y, m1.x + b2v.z, m1.y + b2v.w);
            *(float4*)&out[(size_t)node * ND + 4 * cg] = r;
        }
    }
}

// =================== launcher ===================================================
extern "C" void kernel_launch(void* const* d_in, const int* in_sizes, int n_in,
                              void* d_out, int out_size)
{
    const float* x    = (const float*)d_in[0];
    const int*   ei   = (const int*)  d_in[1];
    const float* ea   = (const float*)d_in[2];
    const float* cong = (const float*)d_in[3];
    const float* mW1  = (const float*)d_in[4];
    const float* mb1  = (const float*)d_in[5];
    const float* mW2  = (const float*)d_in[6];
    const float* mb2  = (const float*)d_in[7];
    const float* uW1  = (const float*)d_in[8];
    const float* ub1  = (const float*)d_in[9];
    const float* uW2  = (const float*)d_in[10];
    const float* ub2  = (const float*)d_in[11];

    int N = in_sizes[0] / ND;
    int E = in_sizes[1] / 2;
    if (N > N_MAX) N = N_MAX;
    if (E > E_MAX) E = E_MAX;

    cudaFuncSetAttribute(k_edge_mma, cudaFuncAttributeMaxDynamicSharedMemorySize, TC_SMEM);
    cudaFuncSetAttribute(k_update,   cudaFuncAttributeMaxDynamicSharedMemorySize, K3_SMEM);

    k_convert  <<<(E + 255) / 256, 256>>>(ei, E);
    k_prep     <<<160, 256>>>(mW1, mW2);
    k_node_pre <<<(N + 31) / 32, 256>>>(x, cong, mW1, mb1, N);
    k_edge_mma <<<(E + 127) / 128, 256, TC_SMEM>>>(ea, mb2, E);
    k_update   <<<(N + 31) / 32, 256, K3_SMEM>>>(x, uW1, ub1, uW2, ub2, (float*)d_out, N);
}

// round 5
// speedup vs baseline: 1.8030x; 1.3849x over previous
#include <cuda_runtime.h>
#include <cuda_bf16.h>
#include <cstdint>

#define ND 128
#define ED 32
#define HD 256
#define N_MAX 100000
#define E_MAX 1600000

typedef unsigned long long u64;
typedef unsigned int u32;

// ---------------- packed f32x2 helpers (scalar kernels) ----------------
__device__ __forceinline__ u64 ffma2(u64 a, u64 b, u64 c) {
    u64 d;
    asm("fma.rn.f32x2 %0, %1, %2, %3;" : "=l"(d) : "l"(a), "l"(b), "l"(c));
    return d;
}
__device__ __forceinline__ u64 dup2(float x) {
    u64 d;
    asm("mov.b64 %0, {%1, %1};" : "=l"(d) : "f"(x));
    return d;
}
__device__ __forceinline__ float2 unpk(u64 p) {
    float2 r;
    asm("mov.b64 {%0, %1}, %2;" : "=f"(r.x), "=f"(r.y) : "l"(p));
    return r;
}

// ---------------- warp-MMA helpers (family-compatible: sm_80+) ----------------
__device__ __forceinline__ u32 smem_u32(const void* p) {
    u32 a;
    asm("{ .reg .u64 t; cvta.to.shared.u64 t, %1; cvt.u32.u64 %0, t; }" : "=r"(a) : "l"(p));
    return a;
}
__device__ __forceinline__ void ldsm_x4(u32 addr, u32& r0, u32& r1, u32& r2, u32& r3) {
    asm volatile("ldmatrix.sync.aligned.m8n8.x4.shared.b16 {%0,%1,%2,%3}, [%4];"
        : "=r"(r0), "=r"(r1), "=r"(r2), "=r"(r3) : "r"(addr));
}
__device__ __forceinline__ void mma_bf16(float* d, u32 a0, u32 a1, u32 a2, u32 a3,
                                         u32 b0, u32 b1) {
    asm volatile("mma.sync.aligned.m16n8k16.row.col.f32.bf16.bf16.f32 "
        "{%0,%1,%2,%3}, {%4,%5,%6,%7}, {%8,%9}, {%0,%1,%2,%3};"
        : "+f"(d[0]), "+f"(d[1]), "+f"(d[2]), "+f"(d[3])
        : "r"(a0), "r"(a1), "r"(a2), "r"(a3), "r"(b0), "r"(b1));
}
__device__ __forceinline__ void bfsplit2(float a, float b, u32& hi, u32& lo) {
    __nv_bfloat162 h = __floats2bfloat162_rn(a, b);
    float ra = a - __bfloat162float(h.x);
    float rb = b - __bfloat162float(h.y);
    __nv_bfloat162 l = __floats2bfloat162_rn(ra, rb);
    hi = *(u32*)&h;
    lo = *(u32*)&l;
}
#define CP_ASYNC16(d, s) asm volatile("cp.async.cg.shared.global [%0], [%1], 16;" :: "r"(d), "l"(s) : "memory")
#define CP_COMMIT()      asm volatile("cp.async.commit_group;" ::: "memory")
#define CP_WAIT(n)       asm volatile("cp.async.wait_group %0;" :: "n"(n) : "memory")

// ---------------- scratch ----------------
__device__ int   g_src[E_MAX];
__device__ int   g_dst[E_MAX];
__device__ float g_Psrc[(size_t)N_MAX * HD];
__device__ float g_Pdst[(size_t)N_MAX * HD];
__device__ float g_agg [(size_t)N_MAX * ND];
// pre-split bf16 weight images (plain row-major, [n][k])
__device__ __align__(16) __nv_bfloat16 g_B1e[256 * 64];   // k<32: W1c_hi, k>=32: W1c_lo
__device__ __align__(16) __nv_bfloat16 g_B2e[128 * 512];  // k<256: W2_hi,  k>=256: W2_lo

// =================== K0: edge_index convert (int64 OR int32) ===================
__global__ void k_convert(const int* __restrict__ w, int E)
{
    __shared__ int s64;
    if (threadIdx.x == 0) {
        int b = 1;
        #pragma unroll
        for (int i = 0; i < 8; i++) if (w[2 * i + 1] != 0) b = 0;
        s64 = b;
    }
    __syncthreads();
    int i = blockIdx.x * blockDim.x + threadIdx.x;
    if (i >= E) return;
    if (s64) {
        const long long* e = (const long long*)w;
        g_src[i] = (int)e[i];
        g_dst[i] = (int)e[(size_t)E + i];
    } else {
        g_src[i] = w[i];
        g_dst[i] = w[(size_t)E + i];
    }
}

// =================== K_prep: build pre-split bf16 weight images =================
__global__ void k_prep(const float* __restrict__ mW1, const float* __restrict__ mW2)
{
    int tid = blockIdx.x * blockDim.x + threadIdx.x;
    int total = 256 * 32 + 128 * 256;
    for (int i = tid; i < total; i += gridDim.x * blockDim.x) {
        if (i < 256 * 32) {
            int n = i >> 5, k = i & 31;                 // W1c[k][n]
            float w = mW1[(size_t)(2 * ND + k) * HD + n];
            __nv_bfloat16 h = __float2bfloat16(w);
            __nv_bfloat16 l = __float2bfloat16(w - __bfloat162float(h));
            g_B1e[n * 64 + k]      = h;
            g_B1e[n * 64 + 32 + k] = l;
        } else {
            int q = i - 256 * 32;
            int n = q >> 8, j = q & 255;                // W2[j][n]
            float w = mW2[(size_t)j * ND + n];
            __nv_bfloat16 h = __float2bfloat16(w);
            __nv_bfloat16 l = __float2bfloat16(w - __bfloat162float(h));
            g_B2e[n * 512 + j]       = h;
            g_B2e[n * 512 + 256 + j] = l;
        }
    }
}

// =================== K1: per-node precompute (scalar, proven) ===================
__global__ __launch_bounds__(256) void k_node_pre(
    const float* __restrict__ x, const float* __restrict__ cong,
    const float* __restrict__ mW1, const float* __restrict__ mb1, int N)
{
    __shared__ __align__(16) float Xt[ND * 33];
    __shared__ __align__(16) float Bs[16 * HD];
    const int tid = threadIdx.x;
    const int cg = tid & 31, eg = tid >> 5;
    const int base = blockIdx.x * 32;

    for (int idx = tid; idx < 32 * ND; idx += 256) {
        int k = idx & (ND - 1), n = idx >> 7;
        int node = base + n;
        Xt[k * 33 + n] = (node < N) ? x[(size_t)node * ND + k] : 0.f;
    }
    float cg4[4];
    #pragma unroll
    for (int i = 0; i < 4; i++) {
        int node = base + eg * 4 + i;
        cg4[i] = (node < N) ? cong[node] : 0.f;
    }
    __syncthreads();

    for (int which = 0; which < 2; which++) {
        const float* W = mW1 + (size_t)which * ND * HD;
        u64 acc[4][2][2];
        #pragma unroll
        for (int i = 0; i < 4; i++)
            #pragma unroll
            for (int p = 0; p < 2; p++) { acc[i][p][0] = 0ull; acc[i][p][1] = 0ull; }

        for (int ko = 0; ko < ND; ko += 16) {
            {
                const float4* srcp = (const float4*)(W + (size_t)ko * HD);
                float4* dstp = (float4*)Bs;
                for (int idx = tid; idx < 16 * HD / 4; idx += 256) dstp[idx] = srcp[idx];
            }
            __syncthreads();
            #pragma unroll 4
            for (int kk = 0; kk < 16; kk++) {
                u64 aa[4];
                #pragma unroll
                for (int i = 0; i < 4; i++) aa[i] = dup2(Xt[(ko + kk) * 33 + eg * 4 + i]);
                #pragma unroll
                for (int p = 0; p < 2; p++) {
                    ulonglong2 b = *(const ulonglong2*)&Bs[kk * HD + 4 * cg + 128 * p];
                    #pragma unroll
                    for (int i = 0; i < 4; i++) {
                        acc[i][p][0] = ffma2(aa[i], b.x, acc[i][p][0]);
                        acc[i][p][1] = ffma2(aa[i], b.y, acc[i][p][1]);
                    }
                }
            }
            __syncthreads();
        }
        #pragma unroll
        for (int p = 0; p < 2; p++) {
            if (which == 0) {
                float4 w2 = *(const float4*)&mW1[(size_t)288 * HD + 128 * p + 4 * cg];
                #pragma unroll
                for (int i = 0; i < 4; i++) {
                    int node = base + eg * 4 + i;
                    if (node < N) {
                        float2 v0 = unpk(acc[i][p][0]), v1 = unpk(acc[i][p][1]);
                        float4 r = make_float4(v0.x + cg4[i] * w2.x, v0.y + cg4[i] * w2.y,
                                               v1.x + cg4[i] * w2.z, v1.y + cg4[i] * w2.w);
                        *(float4*)&g_Psrc[(size_t)node * HD + 128 * p + 4 * cg] = r;
                    }
                }
            } else {
                float4 b1 = *(const float4*)&mb1[128 * p + 4 * cg];
                #pragma unroll
                for (int i = 0; i < 4; i++) {
                    int node = base + eg * 4 + i;
                    if (node < N) {
                        float2 v0 = unpk(acc[i][p][0]), v1 = unpk(acc[i][p][1]);
                        float4 r = make_float4(v0.x + b1.x, v0.y + b1.y,
                                               v1.x + b1.z, v1.y + b1.w);
                        *(float4*)&g_Pdst[(size_t)node * HD + 128 * p + 4 * cg] = r;
                    }
                }
            }
        }
    }
    for (int idx = tid; idx < 32 * ND; idx += 256) {
        int node = base + (idx >> 7);
        if (node < N) g_agg[(size_t)node * ND + (idx & (ND - 1))] = 0.f;
    }
}

// =================== K2: warp-MMA edge kernel (v2: 16 warps, fused chunks) ======
// 128 edges/CTA, 512 threads. Warp w: wm = w&7 (rows 16wm..+15), wn = w>>3 (N half).
// Per 64-col hidden chunk c: layer1 MMA -> gather/relu/split -> layer2 MMA (fused),
// with cp.async double-buffered B2 chunk prefetch.
// smem layout (bytes):
//   B1  @ 0       [256 rows][64 halves + pad]  stride 144    36864
//   A2c @ 36864   [128 rows][64 hi | 64 lo]    stride 272    34816   (A1 aliases here)
//   B2  @ 71680   2 bufs x { hi[128][64] st144 | lo +18432 }  73728
//   src @ 145408  int[128];  dst @ 145920 int[128]
#define B1_OFF  0
#define A2_OFF  36864
#define B2_OFF  71680
#define SRC_OFF 145408
#define DST_OFF 145920
#define EDGE_SMEM 146432
#define B1_ST 144
#define A1_ST 144
#define A2_ST 272
#define B2_ST 144
#define B2_BUF 36864

__global__ __launch_bounds__(512, 1) void k_edge_mma(
    const float* __restrict__ edge_attr, const float* __restrict__ mb2, int E)
{
    extern __shared__ __align__(16) char sm[];
    const u32 smu = smem_u32(sm);
    const int tid = threadIdx.x;
    const int w = tid >> 5, l = tid & 31;
    const int wm = w & 7, wn = w >> 3;
    const int g = l >> 2, t = l & 3;
    const int base = blockIdx.x * 128;
    const char* gB2 = (const char*)g_B2e;

    // ---- prefetch B2 chunk 0 into buf 0 (cp.async) ----
    #pragma unroll
    for (int r = 0; r < 4; r++) {
        int i = tid + 512 * r;
        int row = i >> 4, part = i & 15;
        if (part < 8) {
            CP_ASYNC16(smu + B2_OFF + row * B2_ST + part * 16,
                       gB2 + row * 1024 + part * 16);
        } else {
            int p = part - 8;
            CP_ASYNC16(smu + B2_OFF + 18432 + row * B2_ST + p * 16,
                       gB2 + row * 1024 + 512 + p * 16);
        }
    }
    CP_COMMIT();

    // ---- stage src/dst ----
    if (tid < 128) {
        int e = base + tid;
        ((int*)(sm + SRC_OFF))[tid] = (e < E) ? g_src[e] : 0;
        ((int*)(sm + DST_OFF))[tid] = (e < E) ? g_dst[e] : 0;
    }
    // ---- stage B1 ----
    for (int idx = tid; idx < 256 * 8; idx += 512) {
        int row = idx >> 3, ch = idx & 7;
        *(float4*)(sm + B1_OFF + row * B1_ST + ch * 16) =
            *(const float4*)((const char*)g_B1e + row * 128 + ch * 16);
    }
    // ---- stage A1 (aliases A2c region): split edge_attr to bf16 hi|lo ----
    if (tid < 256) {
        int e = tid >> 1, h = tid & 1;
        char* arow = sm + A2_OFF + e * A1_ST;
        if (base + e < E) {
            const float4* src4 = (const float4*)(edge_attr + (size_t)(base + e) * ED + 16 * h);
            #pragma unroll
            for (int q = 0; q < 4; q++) {
                float4 v = src4[q];
                u32 h0, l0, h1, l1;
                bfsplit2(v.x, v.y, h0, l0);
                bfsplit2(v.z, v.w, h1, l1);
                int k = 16 * h + 4 * q;
                *(u32*)(arow + k * 2)            = h0;
                *(u32*)(arow + (k + 2) * 2)      = h1;
                *(u32*)(arow + (32 + k) * 2)     = l0;
                *(u32*)(arow + (32 + k + 2) * 2) = l1;
            }
        } else {
            #pragma unroll
            for (int q = 0; q < 8; q++) {
                int k = 16 * h + 2 * q;
                *(u32*)(arow + k * 2)        = 0u;
                *(u32*)(arow + (32 + k) * 2) = 0u;
            }
        }
    }
    __syncthreads();

    // per-lane ldmatrix address components
    const int lr   = l & 7;
    const int aRow = 16 * wm + lr + ((l >> 3) & 1) * 8;
    const int aKh  = (l >> 4) * 8;
    const int bRow = lr + (l >> 4) * 8;
    const int bKh  = ((l >> 3) & 1) * 8;
    const u32 a1base = smu + A2_OFF + aRow * A1_ST + aKh * 2;  // A1 alias
    const u32 a2base = smu + A2_OFF + aRow * A2_ST + aKh * 2;

    // A1 fragments (k-tiles: 0=hi k0-15, 1=hi k16-31, 2=lo k0-15, 3=lo k16-31)
    u32 fa[4][4];
    #pragma unroll
    for (int kt = 0; kt < 4; kt++)
        ldsm_x4(a1base + kt * 32, fa[kt][0], fa[kt][1], fa[kt][2], fa[kt][3]);

    // this lane's two edge rows
    const int m0 = 16 * wm + g, m1 = m0 + 8;
    const int vs0 = ((const int*)(sm + SRC_OFF))[m0];
    const int vd0 = ((const int*)(sm + DST_OFF))[m0];
    const int vs1 = ((const int*)(sm + SRC_OFF))[m1];
    const int vd1 = ((const int*)(sm + DST_OFF))[m1];
    char* a2r0 = sm + A2_OFF + m0 * A2_ST;
    char* a2r1 = sm + A2_OFF + m1 * A2_ST;

    float acc2[8][4];
    #pragma unroll
    for (int j = 0; j < 8; j++)
        #pragma unroll
        for (int q = 0; q < 4; q++) acc2[j][q] = 0.f;

    // ================= fused chunk loop =================
    #pragma unroll 1
    for (int c = 0; c < 4; c++) {
        // ---- layer 1: acc1 = EA @ W1c[:, warp's 32 cols of chunk c] ----
        float acc1[4][4];
        #pragma unroll
        for (int j = 0; j < 4; j++)
            #pragma unroll
            for (int q = 0; q < 4; q++) acc1[j][q] = 0.f;

        #pragma unroll
        for (int jp = 0; jp < 2; jp++) {
            u32 bb = smu + B1_OFF + (64 * c + 32 * wn + 16 * jp + bRow) * B1_ST + bKh * 2;
            u32 b0, b1, b2, b3;
            ldsm_x4(bb + 0, b0, b1, b2, b3);      // W1hi k0-15
            mma_bf16(acc1[2 * jp],     fa[0][0], fa[0][1], fa[0][2], fa[0][3], b0, b1);
            mma_bf16(acc1[2 * jp + 1], fa[0][0], fa[0][1], fa[0][2], fa[0][3], b2, b3);
            mma_bf16(acc1[2 * jp],     fa[2][0], fa[2][1], fa[2][2], fa[2][3], b0, b1);
            mma_bf16(acc1[2 * jp + 1], fa[2][0], fa[2][1], fa[2][2], fa[2][3], b2, b3);
            ldsm_x4(bb + 32, b0, b1, b2, b3);     // W1hi k16-31
            mma_bf16(acc1[2 * jp],     fa[1][0], fa[1][1], fa[1][2], fa[1][3], b0, b1);
            mma_bf16(acc1[2 * jp + 1], fa[1][0], fa[1][1], fa[1][2], fa[1][3], b2, b3);
            mma_bf16(acc1[2 * jp],     fa[3][0], fa[3][1], fa[3][2], fa[3][3], b0, b1);
            mma_bf16(acc1[2 * jp + 1], fa[3][0], fa[3][1], fa[3][2], fa[3][3], b2, b3);
            ldsm_x4(bb + 64, b0, b1, b2, b3);     // W1lo k0-15
            mma_bf16(acc1[2 * jp],     fa[0][0], fa[0][1], fa[0][2], fa[0][3], b0, b1);
            mma_bf16(acc1[2 * jp + 1], fa[0][0], fa[0][1], fa[0][2], fa[0][3], b2, b3);
            ldsm_x4(bb + 96, b0, b1, b2, b3);     // W1lo k16-31
            mma_bf16(acc1[2 * jp],     fa[1][0], fa[1][1], fa[1][2], fa[1][3], b0, b1);
            mma_bf16(acc1[2 * jp + 1], fa[1][0], fa[1][1], fa[1][2], fa[1][3], b2, b3);
        }

        // all warps done with previous layer-2 reads (A2c + B2 buf) before overwrite
        __syncthreads();

        // ---- prefetch B2 chunk c+1 into buf (c+1)&1 ----
        if (c < 3) {
            int buf = (c + 1) & 1;
            #pragma unroll
            for (int r = 0; r < 4; r++) {
                int i = tid + 512 * r;
                int row = i >> 4, part = i & 15;
                if (part < 8) {
                    CP_ASYNC16(smu + B2_OFF + buf * B2_BUF + row * B2_ST + part * 16,
                               gB2 + row * 1024 + 128 * (c + 1) + part * 16);
                } else {
                    int p = part - 8;
                    CP_ASYNC16(smu + B2_OFF + buf * B2_BUF + 18432 + row * B2_ST + p * 16,
                               gB2 + row * 1024 + 512 + 128 * (c + 1) + p * 16);
                }
            }
            CP_COMMIT();
        }

        // ---- epilogue: gather node partials, relu, bf16-split into A2c ----
        #pragma unroll
        for (int nt = 0; nt < 4; nt++) {
            int col = 64 * c + 32 * wn + 8 * nt + 2 * t;
            int lc  = 32 * wn + 8 * nt + 2 * t;
            float2 ps0 = *(const float2*)(g_Psrc + (size_t)vs0 * HD + col);
            float2 pd0 = *(const float2*)(g_Pdst + (size_t)vd0 * HD + col);
            float2 ps1 = *(const float2*)(g_Psrc + (size_t)vs1 * HD + col);
            float2 pd1 = *(const float2*)(g_Pdst + (size_t)vd1 * HD + col);
            float v00 = fmaxf(acc1[nt][0] + ps0.x + pd0.x, 0.f);
            float v01 = fmaxf(acc1[nt][1] + ps0.y + pd0.y, 0.f);
            float v10 = fmaxf(acc1[nt][2] + ps1.x + pd1.x, 0.f);
            float v11 = fmaxf(acc1[nt][3] + ps1.y + pd1.y, 0.f);
            u32 h0, l0v, h1, l1v;
            bfsplit2(v00, v01, h0, l0v);
            bfsplit2(v10, v11, h1, l1v);
            *(u32*)(a2r0 + lc * 2)       = h0;
            *(u32*)(a2r0 + 128 + lc * 2) = l0v;
            *(u32*)(a2r1 + lc * 2)       = h1;
            *(u32*)(a2r1 + 128 + lc * 2) = l1v;
        }

        if (c < 3) { CP_WAIT(1); } else { CP_WAIT(0); }
        __syncthreads();

        // ---- layer 2: accumulate h_chunk @ W2_chunk (3-term) into acc2 ----
        const u32 b2b = smu + B2_OFF + (c & 1) * B2_BUF;
        #pragma unroll
        for (int t4 = 0; t4 < 4; t4++) {
            u32 ah0, ah1, ah2, ah3, al0, al1, al2, al3;
            ldsm_x4(a2base + t4 * 32,       ah0, ah1, ah2, ah3);
            ldsm_x4(a2base + 128 + t4 * 32, al0, al1, al2, al3);
            #pragma unroll
            for (int jp = 0; jp < 4; jp++) {
                u32 nrow = (u32)(64 * wn + 16 * jp + bRow);
                u32 kof  = (u32)(16 * t4 + bKh) * 2;
                u32 b0, b1, b2, b3;
                ldsm_x4(b2b + nrow * B2_ST + kof, b0, b1, b2, b3);           // W2hi
                mma_bf16(acc2[2 * jp],     ah0, ah1, ah2, ah3, b0, b1);
                mma_bf16(acc2[2 * jp + 1], ah0, ah1, ah2, ah3, b2, b3);
                mma_bf16(acc2[2 * jp],     al0, al1, al2, al3, b0, b1);
                mma_bf16(acc2[2 * jp + 1], al0, al1, al2, al3, b2, b3);
                ldsm_x4(b2b + 18432 + nrow * B2_ST + kof, b0, b1, b2, b3);   // W2lo
                mma_bf16(acc2[2 * jp],     ah0, ah1, ah2, ah3, b0, b1);
                mma_bf16(acc2[2 * jp + 1], ah0, ah1, ah2, ah3, b2, b3);
            }
        }
    }

    // ---- scatter: + mb2, red.v2 into g_agg[dst] ----
    const bool e0 = (base + m0 < E), e1 = (base + m1 < E);
    #pragma unroll
    for (int j = 0; j < 8; j++) {
        int n = 64 * wn + 8 * j + 2 * t;
        float2 bv = *(const float2*)(mb2 + n);
        if (e0) {
            float x0 = acc2[j][0] + bv.x, x1 = acc2[j][1] + bv.y;
            asm volatile("red.global.add.v2.f32 [%0], {%1, %2};"
                         :: "l"(g_agg + (size_t)vd0 * ND + n), "f"(x0), "f"(x1) : "memory");
        }
        if (e1) {
            float x0 = acc2[j][2] + bv.x, x1 = acc2[j][3] + bv.y;
            asm volatile("red.global.add.v2.f32 [%0], {%1, %2};"
                         :: "l"(g_agg + (size_t)vd1 * ND + n), "f"(x0), "f"(x1) : "memory");
        }
    }
}

// =================== K3: node update MLP (scalar, proven) =======================
#define K3_SMEM (16640 * 4)
__global__ __launch_bounds__(256) void k_update(
    const float* __restrict__ x,
    const float* __restrict__ uW1, const float* __restrict__ ub1,
    const float* __restrict__ uW2, const float* __restrict__ ub2,
    float* __restrict__ out, int N)
{
    extern __shared__ __align__(16) float smf[];
    float* At = smf;
    float* Ht = smf;
    float* Ws = smf + 8448;
    float* B2 = smf + 8448;

    const int tid = threadIdx.x;
    const int cg = tid & 31, eg = tid >> 5;
    const int base = blockIdx.x * 32;

    for (int idx = tid; idx < 32 * HD; idx += 256) {
        int k = idx & (HD - 1), n = idx >> 8;
        int node = base + n;
        float v = 0.f;
        if (node < N)
            v = (k < ND) ? x[(size_t)node * ND + k]
                         : g_agg[(size_t)node * ND + (k - ND)];
        At[k * 33 + n] = v;
    }
    __syncthreads();

    u64 acc[4][2][2];
    #pragma unroll
    for (int i = 0; i < 4; i++)
        #pragma unroll
        for (int p = 0; p < 2; p++) { acc[i][p][0] = 0ull; acc[i][p][1] = 0ull; }

    for (int ko = 0; ko < HD; ko += 32) {
        {
            const float4* srcp = (const float4*)(uW1 + (size_t)ko * HD);
            float4* dstp = (float4*)Ws;
            for (int idx = tid; idx < 32 * HD / 4; idx += 256) dstp[idx] = srcp[idx];
        }
        __syncthreads();
        #pragma unroll 4
        for (int kk = 0; kk < 32; kk++) {
            u64 aa[4];
            #pragma unroll
            for (int i = 0; i < 4; i++) aa[i] = dup2(At[(ko + kk) * 33 + eg * 4 + i]);
            #pragma unroll
            for (int p = 0; p < 2; p++) {
                ulonglong2 b = *(const ulonglong2*)&Ws[kk * HD + 4 * cg + 128 * p];
                #pragma unroll
                for (int i = 0; i < 4; i++) {
                    acc[i][p][0] = ffma2(aa[i], b.x, acc[i][p][0]);
                    acc[i][p][1] = ffma2(aa[i], b.y, acc[i][p][1]);
                }
            }
        }
        __syncthreads();
    }

    #pragma unroll
    for (int p = 0; p < 2; p++) {
        float4 b1 = *(const float4*)&ub1[128 * p + 4 * cg];
        #pragma unroll
        for (int i = 0; i < 4; i++) {
            int n = eg * 4 + i;
            int jb = 128 * p + 4 * cg;
            float2 v0 = unpk(acc[i][p][0]), v1 = unpk(acc[i][p][1]);
            bool ok = (base + n < N);
            Ht[(jb + 0) * 33 + n] = ok ? fmaxf(v0.x + b1.x, 0.f) : 0.f;
            Ht[(jb + 1) * 33 + n] = ok ? fmaxf(v0.y + b1.y, 0.f) : 0.f;
            Ht[(jb + 2) * 33 + n] = ok ? fmaxf(v1.x + b1.z, 0.f) : 0.f;
            Ht[(jb + 3) * 33 + n] = ok ? fmaxf(v1.y + b1.w, 0.f) : 0.f;
        }
    }
    __syncthreads();

    u64 acc2[4][2];
    #pragma unroll
    for (int i = 0; i < 4; i++) { acc2[i][0] = 0ull; acc2[i][1] = 0ull; }

    for (int ko = 0; ko < HD; ko += 32) {
        {
            const float4* srcp = (const float4*)(uW2 + (size_t)ko * ND);
            float4* dstp = (float4*)B2;
            for (int idx = tid; idx < 32 * ND / 4; idx += 256) dstp[idx] = srcp[idx];
        }
        __syncthreads();
        #pragma unroll 4
        for (int kk = 0; kk < 32; kk++) {
            ulonglong2 b = *(const ulonglong2*)&B2[kk * ND + 4 * cg];
            #pragma unroll
            for (int i = 0; i < 4; i++) {
                u64 aa = dup2(Ht[(ko + kk) * 33 + eg * 4 + i]);
                acc2[i][0] = ffma2(aa, b.x, acc2[i][0]);
                acc2[i][1] = ffma2(aa, b.y, acc2[i][1]);
            }
        }
        __syncthreads();
    }

    float4 b2v = *(const float4*)&ub2[4 * cg];
    #pragma unroll
    for (int i = 0; i < 4; i++) {
        int node = base + eg * 4 + i;
        if (node < N) {
            float2 m0 = unpk(acc2[i][0]), m1 = unpk(acc2[i][1]);
            float4 r = make_float4(m0.x + b2v.x, m0.y + b2v.y, m1.x + b2v.z, m1.y + b2v.w);
            *(float4*)&out[(size_t)node * ND + 4 * cg] = r;
        }
    }
}

// =================== launcher ===================================================
extern "C" void kernel_launch(void* const* d_in, const int* in_sizes, int n_in,
                              void* d_out, int out_size)
{
    const float* x    = (const float*)d_in[0];
    const int*   ei   = (const int*)  d_in[1];
    const float* ea   = (const float*)d_in[2];
    const float* cong = (const float*)d_in[3];
    const float* mW1  = (const float*)d_in[4];
    const float* mb1  = (const float*)d_in[5];
    const float* mW2  = (const float*)d_in[6];
    const float* mb2  = (const float*)d_in[7];
    const float* uW1  = (const float*)d_in[8];
    const float* ub1  = (const float*)d_in[9];
    const float* uW2  = (const float*)d_in[10];
    const float* ub2  = (const float*)d_in[11];

    int N = in_sizes[0] / ND;
    int E = in_sizes[1] / 2;
    if (N > N_MAX) N = N_MAX;
    if (E > E_MAX) E = E_MAX;

    cudaFuncSetAttribute(k_edge_mma, cudaFuncAttributeMaxDynamicSharedMemorySize, EDGE_SMEM);
    cudaFuncSetAttribute(k_update,   cudaFuncAttributeMaxDynamicSharedMemorySize, K3_SMEM);

    k_convert  <<<(E + 255) / 256, 256>>>(ei, E);
    k_prep     <<<160, 256>>>(mW1, mW2);
    k_node_pre <<<(N + 31) / 32, 256>>>(x, cong, mW1, mb1, N);
    k_edge_mma <<<(E + 127) / 128, 512, EDGE_SMEM>>>(ea, mb2, E);
    k_update   <<<(N + 31) / 32, 256, K3_SMEM>>>(x, uW1, ub1, uW2, ub2, (float*)d_out, N);
}